// round 3
// baseline (speedup 1.0000x reference)
#include <cuda_runtime.h>

#define NN 4
#define HH 480
#define WW 640

// Scratch (static device arrays; no allocation anywhere)
__device__ float  g_t1[NN * 4 * HH * WW];   // ping
__device__ float  g_t2[NN * 4 * HH * WW];   // pong / theta NHWC4
__device__ float4 g_xt[NN * HH * WW];       // x packed NHWC (c=0..2, w=0)

// ---------------------------------------------------------------------------
// Packed f32x2 helpers (Blackwell)
// ---------------------------------------------------------------------------
typedef unsigned long long u64;

__device__ __forceinline__ u64 pk(float lo, float hi) {
    u64 r; asm("mov.b64 %0, {%1,%2};" : "=l"(r) : "f"(lo), "f"(hi)); return r;
}
__device__ __forceinline__ void upk(u64 v, float& lo, float& hi) {
    asm("mov.b64 {%0,%1}, %2;" : "=f"(lo), "=f"(hi) : "l"(v));
}
__device__ __forceinline__ u64 fma2(u64 a, u64 b, u64 c) {
    u64 d; asm("fma.rn.f32x2 %0, %1, %2, %3;" : "=l"(d) : "l"(a), "l"(b), "l"(c));
    return d;
}

// ---------------------------------------------------------------------------
// Kernel 0: pack x [N,3,H,W] -> NHWC float4 (4th lane zero)
// ---------------------------------------------------------------------------
__global__ void __launch_bounds__(256) pack_x_kernel(const float* __restrict__ x) {
    int idx = blockIdx.x * 256 + threadIdx.x;
    const int total = NN * HH * WW;
    if (idx >= total) return;
    int n  = idx / (HH * WW);
    int hw = idx - n * (HH * WW);
    const float* xb = x + (size_t)n * 3 * HH * WW + hw;
    float4 v;
    v.x = __ldg(&xb[0]);
    v.y = __ldg(&xb[HH * WW]);
    v.z = __ldg(&xb[2 * HH * WW]);
    v.w = 0.f;
    g_xt[idx] = v;
}

// ---------------------------------------------------------------------------
// 5x5 conv, pad 2, OC=4, packed-f32x2 math.
// Block 32x8 = 256 thr. Thread computes 4 ADJACENT px (x = x0 + 4*tx + 0..3),
// so tile tile covers 128x8 outputs. Input row slice per (ic,ky): 8 floats
// = 2x LDS.128; weights duplicated into both f32x2 lanes in smem, 2x LDS.128
// per tap (broadcast). Accumulators: 4 oc x 2 pixel-pairs, packed u64.
// SRC/DST: 0 = external x, 1 = g_t1, 2 = g_t2. NHWC_OUT -> float4 theta.
// ---------------------------------------------------------------------------
template <int IC, int SRC, int DST, bool NHWC_OUT>
__global__ void __launch_bounds__(256) conv5_kernel(
    const float* __restrict__ xin, const float* __restrict__ w,
    const float* __restrict__ b)
{
    __shared__ float tile[IC][12][132];          // halo tile (132*4B = 16B-aligned rows)
    __shared__ ulonglong2 wsh[IC][5][5][2];      // [ic][ky][kx][{oc01,oc23}] dup-lane
    __shared__ float bsh[4];

    const int tx  = threadIdx.x;
    const int ty  = threadIdx.y;
    const int tid = ty * 32 + tx;
    const int x0  = blockIdx.x * 128;
    const int y0  = blockIdx.y * 8;
    const int n   = blockIdx.z;

    const float* in = (SRC == 0) ? xin : (SRC == 1) ? g_t1 : g_t2;
    float* out      = (DST == 1) ? g_t1 : g_t2;

    // weights: src layout [OC=4][IC][5][5] -> dup-lane packed [ic][ky][kx][oc-pair]
    for (int i = tid; i < IC * 25; i += 256) {
        int ic = i / 25;
        int k  = i - ic * 25;          // ky*5+kx
        float w0 = __ldg(&w[(0 * IC + ic) * 25 + k]);
        float w1 = __ldg(&w[(1 * IC + ic) * 25 + k]);
        float w2 = __ldg(&w[(2 * IC + ic) * 25 + k]);
        float w3 = __ldg(&w[(3 * IC + ic) * 25 + k]);
        int ky = k / 5, kx = k - ky * 5;
        wsh[ic][ky][kx][0] = make_ulonglong2(pk(w0, w0), pk(w1, w1));
        wsh[ic][ky][kx][1] = make_ulonglong2(pk(w2, w2), pk(w3, w3));
    }
    if (tid < 4) bsh[tid] = __ldg(&b[tid]);

    // input tile with halo: rows y0-2..y0+9, cols x0-2..x0+129
    const float* inb = in + (size_t)n * IC * HH * WW;
    for (int i = tid; i < IC * 12 * 132; i += 256) {
        int ic = i / (12 * 132);
        int r  = (i / 132) % 12;
        int c  = i % 132;
        int gy = y0 + r - 2;
        int gx = x0 + c - 2;
        float v = 0.f;
        if (gy >= 0 && gy < HH && gx >= 0 && gx < WW)
            v = __ldg(&inb[(size_t)ic * HH * WW + gy * WW + gx]);
        tile[ic][r][c] = v;
    }
    __syncthreads();

    // acc[oc][p]: p=0 -> px{0,1}, p=1 -> px{2,3}
    u64 acc[4][2];
#pragma unroll
    for (int oc = 0; oc < 4; ++oc) {
        u64 bb = pk(bsh[oc], bsh[oc]);
        acc[oc][0] = bb; acc[oc][1] = bb;
    }

#pragma unroll
    for (int ic = 0; ic < IC; ++ic) {
#pragma unroll
        for (int ky = 0; ky < 5; ++ky) {
            const float4 a0 = *reinterpret_cast<const float4*>(&tile[ic][ty + ky][4 * tx]);
            const float4 a1 = *reinterpret_cast<const float4*>(&tile[ic][ty + ky][4 * tx + 4]);
            // pixel pairs p[k] = (v[k], v[k+1]), k = 0..6
            u64 p[7];
            p[0] = pk(a0.x, a0.y); p[1] = pk(a0.y, a0.z); p[2] = pk(a0.z, a0.w);
            p[3] = pk(a0.w, a1.x); p[4] = pk(a1.x, a1.y); p[5] = pk(a1.y, a1.z);
            p[6] = pk(a1.z, a1.w);
#pragma unroll
            for (int kx = 0; kx < 5; ++kx) {
                const ulonglong2 wa = wsh[ic][ky][kx][0];
                const ulonglong2 wb = wsh[ic][ky][kx][1];
                acc[0][0] = fma2(p[kx],     wa.x, acc[0][0]);
                acc[0][1] = fma2(p[kx + 2], wa.x, acc[0][1]);
                acc[1][0] = fma2(p[kx],     wa.y, acc[1][0]);
                acc[1][1] = fma2(p[kx + 2], wa.y, acc[1][1]);
                acc[2][0] = fma2(p[kx],     wb.x, acc[2][0]);
                acc[2][1] = fma2(p[kx + 2], wb.x, acc[2][1]);
                acc[3][0] = fma2(p[kx],     wb.y, acc[3][0]);
                acc[3][1] = fma2(p[kx + 2], wb.y, acc[3][1]);
            }
        }
    }

    const int y  = y0 + ty;
    const int xb = x0 + 4 * tx;
    float o[4][4];
#pragma unroll
    for (int oc = 0; oc < 4; ++oc) {
        upk(acc[oc][0], o[oc][0], o[oc][1]);
        upk(acc[oc][1], o[oc][2], o[oc][3]);
    }

    if (NHWC_OUT) {
        float4* o4 = reinterpret_cast<float4*>(out) + (size_t)n * HH * WW + y * WW + xb;
#pragma unroll
        for (int t = 0; t < 4; ++t)
            o4[t] = make_float4(o[0][t], o[1][t], o[2][t], o[3][t]);
    } else {
#pragma unroll
        for (int oc = 0; oc < 4; ++oc) {
            float4* op = reinterpret_cast<float4*>(
                out + ((size_t)(n * 4 + oc) * HH + y) * WW + xb);
            *op = make_float4(o[oc][0], o[oc][1], o[oc][2], o[oc][3]);
        }
    }
}

// ---------------------------------------------------------------------------
// Fused: grid build + bilinear grid_sample + stride-3 3x3 conv epilogue.
// theta in NHWC float4 (g_t2). x in NHWC float4 (g_xt).
// Thread map: tx -> h (gathers coalesced along x columns), ty -> w.
// ---------------------------------------------------------------------------
__device__ __forceinline__ float4 fetch4(const float4* __restrict__ b, int x, int y) {
    if ((unsigned)x < (unsigned)WW && (unsigned)y < (unsigned)HH)
        return __ldg(&b[y * WW + x]);
    return make_float4(0.f, 0.f, 0.f, 0.f);
}

__global__ void __launch_bounds__(256) stn_sample_kernel(
    const float* __restrict__ wr, const float* __restrict__ br,
    float* __restrict__ out)
{
    __shared__ float wsh[81];
    __shared__ float bsh[3];
    __shared__ float so[3][32][9];

    const int tx  = threadIdx.x;
    const int ty  = threadIdx.y;
    const int tid = ty * 32 + tx;
    if (tid < 81) wsh[tid] = __ldg(&wr[tid]);
    if (tid < 3)  bsh[tid] = __ldg(&br[tid]);
    __syncthreads();

    const int h0 = blockIdx.x * 32;
    const int w0 = blockIdx.y * 8;
    const int n  = blockIdx.z;
    const int h  = h0 + tx;
    const int w  = w0 + ty;

    const float4* tb = reinterpret_cast<const float4*>(g_t2) + (size_t)n * HH * WW;
    const float4* xb = g_xt + (size_t)n * HH * WW;

    const float4 th = __ldg(&tb[h * WW + w]);

    const float yy = -1.f + 2.f * (float)h / (float)(HH - 1);
    const float xx = -1.f + 2.f * (float)w / (float)(WW - 1);

    float acc0 = 0.f, acc1 = 0.f, acc2 = 0.f;

#pragma unroll
    for (int i = 0; i < 3; ++i) {
        const float lyv = (float)(i - 1) * (3.0f / (float)HH);
#pragma unroll
        for (int j = 0; j < 3; ++j) {
            const float lxv = (float)(j - 1) * (3.0f / (float)WW);
            const float gx = yy + th.x * lyv + th.y * lxv;   // grid[...,0] (x coord)
            const float gy = xx + th.z * lyv + th.w * lxv;   // grid[...,1] (y coord)
            const float ix = ((gx + 1.0f) * (float)WW - 1.0f) * 0.5f;
            const float iy = ((gy + 1.0f) * (float)HH - 1.0f) * 0.5f;
            const float ix0 = floorf(ix);
            const float iy0 = floorf(iy);
            const float wx1 = ix - ix0;
            const float wy1 = iy - iy0;
            const float wx0 = 1.0f - wx1;
            const float wy0 = 1.0f - wy1;
            const int xi = (int)ix0;
            const int yi = (int)iy0;

            const float4 v00 = fetch4(xb, xi,     yi);
            const float4 v10 = fetch4(xb, xi + 1, yi);
            const float4 v01 = fetch4(xb, xi,     yi + 1);
            const float4 v11 = fetch4(xb, xi + 1, yi + 1);

            const float w00 = wx0 * wy0, w10 = wx1 * wy0;
            const float w01 = wx0 * wy1, w11 = wx1 * wy1;

            const float vx = v00.x * w00 + v10.x * w10 + v01.x * w01 + v11.x * w11;
            const float vy = v00.y * w00 + v10.y * w10 + v01.y * w01 + v11.y * w11;
            const float vz = v00.z * w00 + v10.z * w10 + v01.z * w01 + v11.z * w11;

            const int k = i * 3 + j;
            acc0 += wsh[0 * 27 + k] * vx + wsh[0 * 27 + 9 + k] * vy + wsh[0 * 27 + 18 + k] * vz;
            acc1 += wsh[1 * 27 + k] * vx + wsh[1 * 27 + 9 + k] * vy + wsh[1 * 27 + 18 + k] * vz;
            acc2 += wsh[2 * 27 + k] * vx + wsh[2 * 27 + 9 + k] * vy + wsh[2 * 27 + 18 + k] * vz;
        }
    }

    so[0][tx][ty] = acc0 + bsh[0];
    so[1][tx][ty] = acc1 + bsh[1];
    so[2][tx][ty] = acc2 + bsh[2];
    __syncthreads();

    for (int e = tid; e < 3 * 32 * 8; e += 256) {
        int oc = e >> 8;
        int r  = (e >> 3) & 31;
        int c  = e & 7;
        out[((size_t)(n * 3 + oc) * HH + h0 + r) * WW + w0 + c] = so[oc][r][c];
    }
}

// ---------------------------------------------------------------------------
extern "C" void kernel_launch(void* const* d_in, const int* in_sizes, int n_in,
                              void* d_out, int out_size)
{
    const float* x  = (const float*)d_in[0];
    const float* w1 = (const float*)d_in[1];
    const float* b1 = (const float*)d_in[2];
    const float* w2 = (const float*)d_in[3];
    const float* b2 = (const float*)d_in[4];
    const float* w3 = (const float*)d_in[5];
    const float* b3 = (const float*)d_in[6];
    const float* w4 = (const float*)d_in[7];
    const float* b4 = (const float*)d_in[8];
    const float* wr = (const float*)d_in[9];
    const float* br = (const float*)d_in[10];
    float* out = (float*)d_out;

    const dim3 cb(32, 8);
    const dim3 cg(WW / 128, HH / 8, NN);     // (5, 60, 4)

    pack_x_kernel<<<(NN * HH * WW + 255) / 256, 256>>>(x);

    conv5_kernel<3, 0, 1, false><<<cg, cb>>>(x, w1, b1);        // x  -> t1
    conv5_kernel<4, 1, 2, false><<<cg, cb>>>(nullptr, w2, b2);  // t1 -> t2
    conv5_kernel<4, 2, 1, false><<<cg, cb>>>(nullptr, w3, b3);  // t2 -> t1
    conv5_kernel<4, 1, 2, true ><<<cg, cb>>>(nullptr, w4, b4);  // t1 -> t2 (theta NHWC4)

    const dim3 sb(32, 8);
    const dim3 sg(HH / 32, WW / 8, NN);      // (15, 80, 4)
    stn_sample_kernel<<<sg, sb>>>(wr, br, out);
}

// round 4
// speedup vs baseline: 1.0756x; 1.0756x over previous
#include <cuda_runtime.h>

#define NN 4
#define HH 480
#define WW 640

// Scratch (static device arrays; no allocation anywhere)
__device__ float  g_t1[NN * 4 * HH * WW];   // ping
__device__ float  g_t2[NN * 4 * HH * WW];   // pong / theta NHWC4
__device__ float4 g_xt[NN * HH * WW];       // x packed NHWC (c=0..2, w=0)

// ---------------------------------------------------------------------------
// Kernel 0: pack x [N,3,H,W] -> NHWC float4 (4th lane zero)
// ---------------------------------------------------------------------------
__global__ void __launch_bounds__(256) pack_x_kernel(const float* __restrict__ x) {
    int idx = blockIdx.x * 256 + threadIdx.x;
    const int total = NN * HH * WW;
    if (idx >= total) return;
    int n  = idx / (HH * WW);
    int hw = idx - n * (HH * WW);
    const float* xb = x + (size_t)n * 3 * HH * WW + hw;
    float4 v;
    v.x = __ldg(&xb[0]);
    v.y = __ldg(&xb[HH * WW]);
    v.z = __ldg(&xb[2 * HH * WW]);
    v.w = 0.f;
    g_xt[idx] = v;
}

// ---------------------------------------------------------------------------
// 5x5 conv, pad 2, OC=4. Block 32x8; thread computes 4 ADJACENT px
// (x = x0 + 4*tx + 0..3) -> tile covers 128x8 outputs.
// tile[ic][r][c] holds input[y0+r-2][x0+c-2]; thread reads cols 4tx..4tx+7
// as two 16B-aligned LDS.128 (row stride 132 floats = 528B = 33*16B).
// Weights as float4 per tap (4 ocs) -> 5 broadcast LDS.128 per (ic,ky) row.
// SRC/DST: 0 = external x, 1 = g_t1, 2 = g_t2. NHWC_OUT -> float4 theta.
// ---------------------------------------------------------------------------
template <int IC, int SRC, int DST, bool NHWC_OUT>
__global__ void __launch_bounds__(256) conv5_kernel(
    const float* __restrict__ xin, const float* __restrict__ w,
    const float* __restrict__ b)
{
    __shared__ float  tile[IC][12][132];
    __shared__ float4 w4[IC][5][5];      // [ic][ky][kx] -> (oc0,oc1,oc2,oc3)
    __shared__ float4 b4s;

    const int tx  = threadIdx.x;
    const int ty  = threadIdx.y;
    const int tid = ty * 32 + tx;
    const int x0  = blockIdx.x * 128;
    const int y0  = blockIdx.y * 8;
    const int n   = blockIdx.z;

    const float* in = (SRC == 0) ? xin : (SRC == 1) ? g_t1 : g_t2;
    float* out      = (DST == 1) ? g_t1 : g_t2;

    // weights: src layout [OC=4][IC][5][5]
    if (tid < IC * 25) {
        int ic = tid / 25;
        int k  = tid - ic * 25;        // ky*5+kx
        int ky = k / 5, kx = k - ky * 5;
        w4[ic][ky][kx] = make_float4(
            __ldg(&w[(0 * IC + ic) * 25 + k]),
            __ldg(&w[(1 * IC + ic) * 25 + k]),
            __ldg(&w[(2 * IC + ic) * 25 + k]),
            __ldg(&w[(3 * IC + ic) * 25 + k]));
    }
    if (tid == 0)
        b4s = make_float4(__ldg(&b[0]), __ldg(&b[1]), __ldg(&b[2]), __ldg(&b[3]));

    // input tile with halo: rows y0-2..y0+9, cols x0-2..x0+129
    const float* inb = in + (size_t)n * IC * HH * WW;
    for (int i = tid; i < IC * 12 * 132; i += 256) {
        int ic = i / (12 * 132);
        int r  = (i / 132) % 12;
        int c  = i % 132;
        int gy = y0 + r - 2;
        int gx = x0 + c - 2;
        float v = 0.f;
        if (gy >= 0 && gy < HH && gx >= 0 && gx < WW)
            v = __ldg(&inb[(size_t)ic * HH * WW + gy * WW + gx]);
        tile[ic][r][c] = v;
    }
    __syncthreads();

    // acc[oc][px]
    float acc[4][4];
    {
        const float4 bb = b4s;
#pragma unroll
        for (int p = 0; p < 4; ++p) {
            acc[0][p] = bb.x; acc[1][p] = bb.y;
            acc[2][p] = bb.z; acc[3][p] = bb.w;
        }
    }

#pragma unroll 1
    for (int ic = 0; ic < IC; ++ic) {
#pragma unroll
        for (int ky = 0; ky < 5; ++ky) {
            const float4* rowp =
                reinterpret_cast<const float4*>(&tile[ic][ty + ky][4 * tx]);
            const float4 a0 = rowp[0];
            const float4 a1 = rowp[1];
            const float v[8] = {a0.x, a0.y, a0.z, a0.w, a1.x, a1.y, a1.z, a1.w};
#pragma unroll
            for (int kx = 0; kx < 5; ++kx) {
                const float4 wv = w4[ic][ky][kx];
#pragma unroll
                for (int p = 0; p < 4; ++p) {
                    const float x = v[p + kx];
                    acc[0][p] += x * wv.x;
                    acc[1][p] += x * wv.y;
                    acc[2][p] += x * wv.z;
                    acc[3][p] += x * wv.w;
                }
            }
        }
    }

    const int y  = y0 + ty;
    const int xb = x0 + 4 * tx;

    if (NHWC_OUT) {
        float4* o4 = reinterpret_cast<float4*>(out) + (size_t)n * HH * WW + y * WW + xb;
#pragma unroll
        for (int p = 0; p < 4; ++p)
            o4[p] = make_float4(acc[0][p], acc[1][p], acc[2][p], acc[3][p]);
    } else {
#pragma unroll
        for (int oc = 0; oc < 4; ++oc) {
            float4* op = reinterpret_cast<float4*>(
                out + ((size_t)(n * 4 + oc) * HH + y) * WW + xb);
            *op = make_float4(acc[oc][0], acc[oc][1], acc[oc][2], acc[oc][3]);
        }
    }
}

// ---------------------------------------------------------------------------
// Fused: grid build + bilinear grid_sample + stride-3 3x3 conv epilogue.
// theta in NHWC float4 (g_t2). x in NHWC float4 (g_xt).
// Thread map: tx -> h (gathers coalesced along x columns), ty -> w.
// ---------------------------------------------------------------------------
__device__ __forceinline__ float4 fetch4(const float4* __restrict__ b, int x, int y) {
    if ((unsigned)x < (unsigned)WW && (unsigned)y < (unsigned)HH)
        return __ldg(&b[y * WW + x]);
    return make_float4(0.f, 0.f, 0.f, 0.f);
}

__global__ void __launch_bounds__(256) stn_sample_kernel(
    const float* __restrict__ wr, const float* __restrict__ br,
    float* __restrict__ out)
{
    __shared__ float wsh[81];
    __shared__ float bsh[3];
    __shared__ float so[3][32][9];

    const int tx  = threadIdx.x;
    const int ty  = threadIdx.y;
    const int tid = ty * 32 + tx;
    if (tid < 81) wsh[tid] = __ldg(&wr[tid]);
    if (tid < 3)  bsh[tid] = __ldg(&br[tid]);
    __syncthreads();

    const int h0 = blockIdx.x * 32;
    const int w0 = blockIdx.y * 8;
    const int n  = blockIdx.z;
    const int h  = h0 + tx;
    const int w  = w0 + ty;

    const float4* tb = reinterpret_cast<const float4*>(g_t2) + (size_t)n * HH * WW;
    const float4* xb = g_xt + (size_t)n * HH * WW;

    const float4 th = __ldg(&tb[h * WW + w]);

    const float yy = -1.f + 2.f * (float)h / (float)(HH - 1);
    const float xx = -1.f + 2.f * (float)w / (float)(WW - 1);

    float acc0 = 0.f, acc1 = 0.f, acc2 = 0.f;

#pragma unroll
    for (int i = 0; i < 3; ++i) {
        const float lyv = (float)(i - 1) * (3.0f / (float)HH);
#pragma unroll
        for (int j = 0; j < 3; ++j) {
            const float lxv = (float)(j - 1) * (3.0f / (float)WW);
            const float gx = yy + th.x * lyv + th.y * lxv;   // grid[...,0] (x coord)
            const float gy = xx + th.z * lyv + th.w * lxv;   // grid[...,1] (y coord)
            const float ix = ((gx + 1.0f) * (float)WW - 1.0f) * 0.5f;
            const float iy = ((gy + 1.0f) * (float)HH - 1.0f) * 0.5f;
            const float ix0 = floorf(ix);
            const float iy0 = floorf(iy);
            const float wx1 = ix - ix0;
            const float wy1 = iy - iy0;
            const float wx0 = 1.0f - wx1;
            const float wy0 = 1.0f - wy1;
            const int xi = (int)ix0;
            const int yi = (int)iy0;

            const float4 v00 = fetch4(xb, xi,     yi);
            const float4 v10 = fetch4(xb, xi + 1, yi);
            const float4 v01 = fetch4(xb, xi,     yi + 1);
            const float4 v11 = fetch4(xb, xi + 1, yi + 1);

            const float w00 = wx0 * wy0, w10 = wx1 * wy0;
            const float w01 = wx0 * wy1, w11 = wx1 * wy1;

            const float vx = v00.x * w00 + v10.x * w10 + v01.x * w01 + v11.x * w11;
            const float vy = v00.y * w00 + v10.y * w10 + v01.y * w01 + v11.y * w11;
            const float vz = v00.z * w00 + v10.z * w10 + v01.z * w01 + v11.z * w11;

            const int k = i * 3 + j;
            acc0 += wsh[0 * 27 + k] * vx + wsh[0 * 27 + 9 + k] * vy + wsh[0 * 27 + 18 + k] * vz;
            acc1 += wsh[1 * 27 + k] * vx + wsh[1 * 27 + 9 + k] * vy + wsh[1 * 27 + 18 + k] * vz;
            acc2 += wsh[2 * 27 + k] * vx + wsh[2 * 27 + 9 + k] * vy + wsh[2 * 27 + 18 + k] * vz;
        }
    }

    so[0][tx][ty] = acc0 + bsh[0];
    so[1][tx][ty] = acc1 + bsh[1];
    so[2][tx][ty] = acc2 + bsh[2];
    __syncthreads();

    for (int e = tid; e < 3 * 32 * 8; e += 256) {
        int oc = e >> 8;
        int r  = (e >> 3) & 31;
        int c  = e & 7;
        out[((size_t)(n * 3 + oc) * HH + h0 + r) * WW + w0 + c] = so[oc][r][c];
    }
}

// ---------------------------------------------------------------------------
extern "C" void kernel_launch(void* const* d_in, const int* in_sizes, int n_in,
                              void* d_out, int out_size)
{
    const float* x  = (const float*)d_in[0];
    const float* w1 = (const float*)d_in[1];
    const float* b1 = (const float*)d_in[2];
    const float* w2 = (const float*)d_in[3];
    const float* b2 = (const float*)d_in[4];
    const float* w3 = (const float*)d_in[5];
    const float* b3 = (const float*)d_in[6];
    const float* w4 = (const float*)d_in[7];
    const float* b4 = (const float*)d_in[8];
    const float* wr = (const float*)d_in[9];
    const float* br = (const float*)d_in[10];
    float* out = (float*)d_out;

    const dim3 cb(32, 8);
    const dim3 cg(WW / 128, HH / 8, NN);     // (5, 60, 4)

    pack_x_kernel<<<(NN * HH * WW + 255) / 256, 256>>>(x);

    conv5_kernel<3, 0, 1, false><<<cg, cb>>>(x, w1, b1);        // x  -> t1
    conv5_kernel<4, 1, 2, false><<<cg, cb>>>(nullptr, w2, b2);  // t1 -> t2
    conv5_kernel<4, 2, 1, false><<<cg, cb>>>(nullptr, w3, b3);  // t2 -> t1
    conv5_kernel<4, 1, 2, true ><<<cg, cb>>>(nullptr, w4, b4);  // t1 -> t2 (theta NHWC4)

    const dim3 sb(32, 8);
    const dim3 sg(HH / 32, WW / 8, NN);      // (15, 80, 4)
    stn_sample_kernel<<<sg, sb>>>(wr, br, out);
}